// round 12
// baseline (speedup 1.0000x reference)
#include <cuda_runtime.h>
#include <cuda_bf16.h>
#include <math.h>
#include <stdint.h>

#define S_LEN 2048
#define HID   4096
#define NQH   32
#define NKVH  8
#define HD    128
#define QKV_N 6144
#define KV_OFF 4096
#define V_OFF  5120
#define Q_SIZE 4096

// ---------------- scratch (device globals, allocation-free) ----------------
__device__ float         g_qkv[S_LEN * QKV_N];
__device__ __nv_bfloat16 g_xn_hi[S_LEN * HID];
__device__ __nv_bfloat16 g_xn_mid[S_LEN * HID];
__device__ __nv_bfloat16 g_wqkv_hi[QKV_N * HID];
__device__ __nv_bfloat16 g_wqkv_mid[QKV_N * HID];
__device__ __nv_bfloat16 g_wo_hi[Q_SIZE * HID];
__device__ __nv_bfloat16 g_wo_mid[Q_SIZE * HID];
__device__ __nv_bfloat16 g_attn_hi[S_LEN * Q_SIZE];
__device__ __nv_bfloat16 g_attn_mid[S_LEN * Q_SIZE];

// ---------------- helpers ----------------
__device__ __forceinline__ uint32_t smem_u32(const void* p) {
    uint32_t a;
    asm("{ .reg .u64 t; cvta.to.shared.u64 t, %1; cvt.u32.u64 %0, t; }" : "=r"(a) : "l"(p));
    return a;
}
__device__ __forceinline__ void cp_async16(uint32_t dst, const void* src) {
    asm volatile("cp.async.cg.shared.global [%0], [%1], 16;" :: "r"(dst), "l"(src) : "memory");
}
__device__ __forceinline__ void cp_commit() { asm volatile("cp.async.commit_group;" ::: "memory"); }
__device__ __forceinline__ void cp_wait1() { asm volatile("cp.async.wait_group 1;" ::: "memory"); }
__device__ __forceinline__ void cp_wait0() { asm volatile("cp.async.wait_group 0;" ::: "memory"); }

#define LDSM4(r, addr)                                                             \
    asm volatile("ldmatrix.sync.aligned.m8n8.x4.shared.b16 {%0,%1,%2,%3}, [%4];"   \
        : "=r"((r)[0]), "=r"((r)[1]), "=r"((r)[2]), "=r"((r)[3]) : "r"(addr))

#define LDSM4T(r, addr)                                                                 \
    asm volatile("ldmatrix.sync.aligned.m8n8.x4.trans.shared.b16 {%0,%1,%2,%3}, [%4];"  \
        : "=r"((r)[0]), "=r"((r)[1]), "=r"((r)[2]), "=r"((r)[3]) : "r"(addr))

#define MMA16816(d, a, b0, b1)                                                     \
    asm volatile("mma.sync.aligned.m16n8k16.row.col.f32.bf16.bf16.f32 "            \
        "{%0,%1,%2,%3}, {%4,%5,%6,%7}, {%8,%9}, {%0,%1,%2,%3};"                    \
        : "+f"((d)[0]), "+f"((d)[1]), "+f"((d)[2]), "+f"((d)[3])                   \
        : "r"((a)[0]), "r"((a)[1]), "r"((a)[2]), "r"((a)[3]), "r"(b0), "r"(b1))

__device__ __forceinline__ void split2(float a, float b, uint32_t& hi, uint32_t& mid) {
    __nv_bfloat16 ha = __float2bfloat16(a), hb = __float2bfloat16(b);
    __nv_bfloat16 ma = __float2bfloat16(a - __bfloat162float(ha));
    __nv_bfloat16 mb = __float2bfloat16(b - __bfloat162float(hb));
    __nv_bfloat162 hv; hv.x = ha; hv.y = hb;
    __nv_bfloat162 mv; mv.x = ma; mv.y = mb;
    hi = *(uint32_t*)&hv; mid = *(uint32_t*)&mv;
}

// ---------------------------------------------------------------------------
// RMSNorm -> split bf16 (hi, mid)
// ---------------------------------------------------------------------------
__global__ __launch_bounds__(256) void rmsnorm_kernel(const float* __restrict__ x,
                                                      const float* __restrict__ w) {
    int row = blockIdx.x;
    int t = threadIdx.x;
    const float4* xr = (const float4*)(x + (size_t)row * HID);
    float4 v[4];
    float ss = 0.f;
#pragma unroll
    for (int i = 0; i < 4; i++) {
        v[i] = xr[t + i * 256];
        ss += v[i].x * v[i].x + v[i].y * v[i].y + v[i].z * v[i].z + v[i].w * v[i].w;
    }
    __shared__ float red[8];
#pragma unroll
    for (int o = 16; o > 0; o >>= 1) ss += __shfl_xor_sync(0xffffffffu, ss, o);
    if ((t & 31) == 0) red[t >> 5] = ss;
    __syncthreads();
    if (t < 8) {
        float s2 = red[t];
#pragma unroll
        for (int o = 4; o > 0; o >>= 1) s2 += __shfl_xor_sync(0xffu, s2, o);
        if (t == 0) red[0] = s2;
    }
    __syncthreads();
    float inv = rsqrtf(red[0] / (float)HID + 1e-5f);
    const float4* wr = (const float4*)w;
    __nv_bfloat16* oh = g_xn_hi + (size_t)row * HID;
    __nv_bfloat16* om = g_xn_mid + (size_t)row * HID;
#pragma unroll
    for (int i = 0; i < 4; i++) {
        float4 wv = wr[t + i * 256];
        float f[4];
        f[0] = v[i].x * inv * wv.x; f[1] = v[i].y * inv * wv.y;
        f[2] = v[i].z * inv * wv.z; f[3] = v[i].w * inv * wv.w;
        int base = (t + i * 256) * 4;
        uint32_t h0, m0, h1, m1;
        split2(f[0], f[1], h0, m0);
        split2(f[2], f[3], h1, m1);
        *(uint32_t*)(oh + base)     = h0;
        *(uint32_t*)(oh + base + 2) = h1;
        *(uint32_t*)(om + base)     = m0;
        *(uint32_t*)(om + base + 2) = m1;
    }
}

// ---------------------------------------------------------------------------
// fp32 -> (hi, mid) bf16 split
// ---------------------------------------------------------------------------
__global__ __launch_bounds__(256) void split_kernel(const float* __restrict__ s,
                                                    __nv_bfloat16* __restrict__ hi,
                                                    __nv_bfloat16* __restrict__ mid, int n4) {
    int i = blockIdx.x * 256 + threadIdx.x;
    if (i >= n4) return;
    float4 v = ((const float4*)s)[i];
    uint32_t h0, m0, h1, m1;
    split2(v.x, v.y, h0, m0);
    split2(v.z, v.w, h1, m1);
    *(uint32_t*)(hi + i*4)      = h0;
    *(uint32_t*)(hi + i*4 + 2)  = h1;
    *(uint32_t*)(mid + i*4)     = m0;
    *(uint32_t*)(mid + i*4 + 2) = m1;
}

// ---------------------------------------------------------------------------
// mma.sync bf16-split GEMM:  C[m][n] = sum_k A[m][k]*B[n][k]
// 128x128 tile, BK=32, 8 warps (4x2), 3-stage cp.async, 1 sync/iter,
// double-buffered register fragments. 1 CTA/SM.
// ---------------------------------------------------------------------------
#define GK   32
#define TSTR 80
#define TILE_B (128 * TSTR)
#define STAGE_B (4 * TILE_B)
#define GEMM_SMEM (3 * STAGE_B)     // 122880

struct Frags {
    uint32_t ah[2][4], am[2][4];
    uint32_t bh[4][4], bm[4][4];
};

__device__ __forceinline__ void gemm_load_stage(uint32_t sbase, int buf,
                                                const __nv_bfloat16* g0, const __nv_bfloat16* g1,
                                                const __nv_bfloat16* g2, const __nv_bfloat16* g3,
                                                int K, int kc, int lr, int lseg) {
    uint32_t base = sbase + buf * STAGE_B + lr * TSTR + lseg * 16;
    const __nv_bfloat16* gs[4] = {g0, g1, g2, g3};
#pragma unroll
    for (int mt = 0; mt < 4; mt++) {
        const __nv_bfloat16* g = gs[mt] + (size_t)lr * K + kc + lseg * 8;
        uint32_t d = base + mt * TILE_B;
        cp_async16(d, g);
        cp_async16(d + 64 * TSTR, g + (size_t)64 * K);
    }
}

__device__ __forceinline__ void load_frags(uint32_t st, int kk, int lane, int wm, int wn, Frags& f) {
    int kbA = kk * 32 + ((lane >> 4) << 4);
#pragma unroll
    for (int mf = 0; mf < 2; mf++) {
        uint32_t addr = st + (uint32_t)(wm * 32 + mf * 16 + (lane & 15)) * TSTR + kbA;
        LDSM4(f.ah[mf], addr);
        LDSM4(f.am[mf], addr + TILE_B);
    }
    int q = lane >> 3;
    int nbase = wn * 64 + ((q & 2) << 2) + (lane & 7);
    int kbB = kk * 32 + ((q & 1) << 4);
#pragma unroll
    for (int g = 0; g < 4; g++) {
        uint32_t addr = st + 2 * TILE_B + (uint32_t)(nbase + g * 16) * TSTR + kbB;
        LDSM4(f.bh[g], addr);
        LDSM4(f.bm[g], addr + TILE_B);
    }
}

__device__ __forceinline__ void do_mmas(const Frags& f, float acc[2][8][4]) {
#pragma unroll
    for (int mf = 0; mf < 2; mf++) {
#pragma unroll
        for (int nf = 0; nf < 8; nf++) {
            int g = nf >> 1, j = (nf & 1) * 2;
            MMA16816(acc[mf][nf], f.ah[mf], f.bh[g][j], f.bh[g][j + 1]);
            MMA16816(acc[mf][nf], f.ah[mf], f.bm[g][j], f.bm[g][j + 1]);
            MMA16816(acc[mf][nf], f.am[mf], f.bh[g][j], f.bh[g][j + 1]);
        }
    }
}

__global__ __launch_bounds__(256, 1) void gemm_mma_kernel(
    const __nv_bfloat16* __restrict__ Ah, const __nv_bfloat16* __restrict__ Am,
    const __nv_bfloat16* __restrict__ Bh, const __nv_bfloat16* __restrict__ Bm,
    float* __restrict__ C, int K, int N)
{
    extern __shared__ char smem[];
    int t = threadIdx.x;
    int lane = t & 31, warp = t >> 5;
    int wm = warp & 3, wn = warp >> 2;
    int m0 = blockIdx.y * 128, n0 = blockIdx.x * 128;

    const __nv_bfloat16* gA_h = Ah + (size_t)m0 * K;
    const __nv_bfloat16* gA_m = Am + (size_t)m0 * K;
    const __nv_bfloat16* gB_h = Bh + (size_t)n0 * K;
    const __nv_bfloat16* gB_m = Bm + (size_t)n0 * K;
    uint32_t sbase = smem_u32(smem);
    int lr = t >> 2, lseg = t & 3;

    float acc[2][8][4];
#pragma unroll
    for (int i = 0; i < 2; i++)
#pragma unroll
        for (int j = 0; j < 8; j++)
#pragma unroll
            for (int q = 0; q < 4; q++) acc[i][j][q] = 0.f;

    int NC = K / GK;

    // prologue: stages 0, 1
    gemm_load_stage(sbase, 0, gA_h, gA_m, gB_h, gB_m, K, 0, lr, lseg);
    cp_commit();
    gemm_load_stage(sbase, 1, gA_h, gA_m, gB_h, gB_m, K, GK, lr, lseg);
    cp_commit();

    Frags fr[2];

    for (int c = 0; c < NC; c++) {
        cp_wait1();            // stage c arrived (stage c+1 may still be in flight)
        __syncthreads();       // all warps done reading stage c-1; smem visible
        if (c + 2 < NC) {      // refill the buffer read at iter c-1
            gemm_load_stage(sbase, (c + 2) % 3, gA_h, gA_m, gB_h, gB_m, K, (c + 2) * GK, lr, lseg);
            cp_commit();
        }
        uint32_t st = sbase + (c % 3) * STAGE_B;
        load_frags(st, 0, lane, wm, wn, fr[0]);
        load_frags(st, 1, lane, wm, wn, fr[1]);   // issues under fr[0]'s MMAs
        do_mmas(fr[0], acc);
        do_mmas(fr[1], acc);
    }

    cp_wait0();

#pragma unroll
    for (int mf = 0; mf < 2; mf++) {
#pragma unroll
        for (int nf = 0; nf < 8; nf++) {
            int r = m0 + wm * 32 + mf * 16 + (lane >> 2);
            int cc = n0 + wn * 64 + nf * 8 + (lane & 3) * 2;
            *(float2*)&C[(size_t)r * N + cc]       = make_float2(acc[mf][nf][0], acc[mf][nf][1]);
            *(float2*)&C[(size_t)(r + 8) * N + cc] = make_float2(acc[mf][nf][2], acc[mf][nf][3]);
        }
    }
}

// ---------------------------------------------------------------------------
// RoPE in-place on Q/K in g_qkv (fp32)
// ---------------------------------------------------------------------------
__global__ __launch_bounds__(64) void rope_kernel(const int* __restrict__ positions) {
    int s = blockIdx.x;
    int h = blockIdx.y;
    int d = threadIdx.x;
    float pos = (float)positions[s];
    float invf = powf(10000.0f, -((float)(2 * d)) / 128.0f);
    float f = pos * invf;
    float c = cosf(f), sn = sinf(f);
    float* base;
    if (h < NQH) base = g_qkv + (size_t)s * QKV_N + h * HD;
    else         base = g_qkv + (size_t)s * QKV_N + KV_OFF + (h - NQH) * HD;
    float x1 = base[d];
    float x2 = base[d + 64];
    base[d]      = x1 * c - x2 * sn;
    base[d + 64] = x2 * c + x1 * sn;
}

// ---------------------------------------------------------------------------
// Tensorized flash attention (causal, GQA 4:1), bf16 hi/mid split HMMA.
// CTA: 128 q-rows x 1 head. 8 warps, each m16 x n64 per kv tile of 64.
// ---------------------------------------------------------------------------
#define FSTR 272
#define FQ_B  (128 * FSTR)   // 34816
#define FK_B  (64 * FSTR)    // 17408
#define FLASH_SMEM (2 * FQ_B + 4 * FK_B)   // 139264

__global__ __launch_bounds__(256) void flash_mma_kernel() {
    extern __shared__ char fsm[];
    char* sQh = fsm;
    char* sKh = fsm + 2 * FQ_B;
    char* sVh = fsm + 2 * FQ_B + 2 * FK_B;

    int qt = 15 - (int)blockIdx.x;        // heavy tiles first
    int h  = blockIdx.y;
    int kvh = h >> 2;
    int t = threadIdx.x;
    int lane = t & 31, wid = t >> 5;
    int q0 = qt * 128;
    const float scale = 0.08838834764831845f;

    uint32_t uQh = smem_u32(sQh);
    uint32_t uKh = smem_u32(sKh);
    uint32_t uVh = smem_u32(sVh);

    // load Q tile (128 rows x 32 float4-chunks = 4096 -> 16 iters), fold scale, split hi/mid
    {
        const float* gq = g_qkv + (size_t)q0 * QKV_N + h * HD;
#pragma unroll
        for (int i = 0; i < 16; i++) {
            int idx = t + i * 256;
            int r = idx >> 5, c4 = idx & 31;
            float4 v = *(const float4*)(gq + (size_t)r * QKV_N + c4 * 4);
            uint32_t h0, m0, h1, m1;
            split2(v.x * scale, v.y * scale, h0, m0);
            split2(v.z * scale, v.w * scale, h1, m1);
            uint32_t off = (uint32_t)r * FSTR + c4 * 8;
            *(uint2*)(sQh + off)        = make_uint2(h0, h1);
            *(uint2*)(sQh + FQ_B + off) = make_uint2(m0, m1);
        }
    }

    float rm0 = -1e30f, rm1 = -1e30f, rl0 = 0.f, rl1 = 0.f;
    float o[16][4];
#pragma unroll
    for (int i = 0; i < 16; i++)
#pragma unroll
        for (int j = 0; j < 4; j++) o[i][j] = 0.f;

    int ktmax = 2 * qt + 1;
    for (int kt = 0; kt <= ktmax; kt++) {
        int n0 = kt * 64;
        __syncthreads();
        const float* gk = g_qkv + (size_t)n0 * QKV_N + KV_OFF + kvh * HD;
        const float* gv = g_qkv + (size_t)n0 * QKV_N + V_OFF + kvh * HD;
#pragma unroll
        for (int i = 0; i < 8; i++) {
            int idx = t + i * 256;       // 2048 = 64 rows x 32 float4-chunks
            int r = idx >> 5, c4 = idx & 31;
            uint32_t off = (uint32_t)r * FSTR + c4 * 8;
            float4 kv4 = *(const float4*)(gk + (size_t)r * QKV_N + c4 * 4);
            uint32_t h0, m0, h1, m1;
            split2(kv4.x, kv4.y, h0, m0);
            split2(kv4.z, kv4.w, h1, m1);
            *(uint2*)(sKh + off)        = make_uint2(h0, h1);
            *(uint2*)(sKh + FK_B + off) = make_uint2(m0, m1);
            float4 vv4 = *(const float4*)(gv + (size_t)r * QKV_N + c4 * 4);
            split2(vv4.x, vv4.y, h0, m0);
            split2(vv4.z, vv4.w, h1, m1);
            *(uint2*)(sVh + off)        = make_uint2(h0, h1);
            *(uint2*)(sVh + FK_B + off) = make_uint2(m0, m1);
        }
        __syncthreads();

        // S = Q K^T  (warp: m16 x n64)
        float s[8][4];
#pragma unroll
        for (int i = 0; i < 8; i++)
#pragma unroll
            for (int j = 0; j < 4; j++) s[i][j] = 0.f;

        int q = lane >> 3;
        uint32_t brow = ((q & 2) << 2) + (lane & 7);
        uint32_t bko  = (uint32_t)((q & 1) << 4);
#pragma unroll
        for (int kc = 0; kc < 8; kc++) {
            uint32_t ah[4], am[4];
            uint32_t aaddr = uQh + (uint32_t)(wid * 16 + (lane & 15)) * FSTR + kc * 32 + ((lane >> 4) << 4);
            LDSM4(ah, aaddr);
            LDSM4(am, aaddr + FQ_B);
#pragma unroll
            for (int g = 0; g < 4; g++) {
                uint32_t bh[4], bm[4];
                uint32_t baddr = uKh + (uint32_t)(g * 16 + brow) * FSTR + kc * 32 + bko;
                LDSM4(bh, baddr);
                LDSM4(bm, baddr + FK_B);
                MMA16816(s[2*g],   ah, bh[0], bh[1]);
                MMA16816(s[2*g],   ah, bm[0], bm[1]);
                MMA16816(s[2*g],   am, bh[0], bh[1]);
                MMA16816(s[2*g+1], ah, bh[2], bh[3]);
                MMA16816(s[2*g+1], ah, bm[2], bm[3]);
                MMA16816(s[2*g+1], am, bh[2], bh[3]);
            }
        }

        int r0g = q0 + wid * 16 + (lane >> 2);
        if (kt >= 2 * qt) {
#pragma unroll
            for (int nf = 0; nf < 8; nf++) {
                int c0 = n0 + nf * 8 + (lane & 3) * 2;
                if (c0     > r0g)     s[nf][0] = -1e30f;
                if (c0 + 1 > r0g)     s[nf][1] = -1e30f;
                if (c0     > r0g + 8) s[nf][2] = -1e30f;
                if (c0 + 1 > r0g + 8) s[nf][3] = -1e30f;
            }
        }
        float mx0 = -1e30f, mx1 = -1e30f;
#pragma unroll
        for (int nf = 0; nf < 8; nf++) {
            mx0 = fmaxf(mx0, fmaxf(s[nf][0], s[nf][1]));
            mx1 = fmaxf(mx1, fmaxf(s[nf][2], s[nf][3]));
        }
        mx0 = fmaxf(mx0, __shfl_xor_sync(0xffffffffu, mx0, 1));
        mx0 = fmaxf(mx0, __shfl_xor_sync(0xffffffffu, mx0, 2));
        mx1 = fmaxf(mx1, __shfl_xor_sync(0xffffffffu, mx1, 1));
        mx1 = fmaxf(mx1, __shfl_xor_sync(0xffffffffu, mx1, 2));
        float mn0 = fmaxf(rm0, mx0), mn1 = fmaxf(rm1, mx1);
        float cr0 = __expf(rm0 - mn0), cr1 = __expf(rm1 - mn1);
        rm0 = mn0; rm1 = mn1;

        uint32_t pah[4][4], pam[4][4];
        float ls0 = 0.f, ls1 = 0.f;
#pragma unroll
        for (int g = 0; g < 4; g++) {
            float pA0 = __expf(s[2*g][0]   - mn0), pA1 = __expf(s[2*g][1]   - mn0);
            float pA2 = __expf(s[2*g][2]   - mn1), pA3 = __expf(s[2*g][3]   - mn1);
            float pB0 = __expf(s[2*g+1][0] - mn0), pB1 = __expf(s[2*g+1][1] - mn0);
            float pB2 = __expf(s[2*g+1][2] - mn1), pB3 = __expf(s[2*g+1][3] - mn1);
            ls0 += pA0 + pA1 + pB0 + pB1;
            ls1 += pA2 + pA3 + pB2 + pB3;
            split2(pA0, pA1, pah[g][0], pam[g][0]);
            split2(pA2, pA3, pah[g][1], pam[g][1]);
            split2(pB0, pB1, pah[g][2], pam[g][2]);
            split2(pB2, pB3, pah[g][3], pam[g][3]);
        }
        ls0 += __shfl_xor_sync(0xffffffffu, ls0, 1);
        ls0 += __shfl_xor_sync(0xffffffffu, ls0, 2);
        ls1 += __shfl_xor_sync(0xffffffffu, ls1, 1);
        ls1 += __shfl_xor_sync(0xffffffffu, ls1, 2);
        rl0 = rl0 * cr0 + ls0;
        rl1 = rl1 * cr1 + ls1;

#pragma unroll
        for (int nf = 0; nf < 16; nf++) {
            o[nf][0] *= cr0; o[nf][1] *= cr0;
            o[nf][2] *= cr1; o[nf][3] *= cr1;
        }

        // O += P V   (B frags via ldmatrix.trans on V[kv][d])
#pragma unroll
        for (int g = 0; g < 4; g++) {
#pragma unroll
            for (int dg = 0; dg < 8; dg++) {
                uint32_t bh[4], bm[4];
                uint32_t vaddr = uVh + (uint32_t)(g * 16 + (lane & 15)) * FSTR + dg * 32 + ((lane >> 4) << 4);
                LDSM4T(bh, vaddr);
                LDSM4T(bm, vaddr + FK_B);
                MMA16816(o[2*dg],   pah[g], bh[0], bh[1]);
                MMA16816(o[2*dg],   pah[g], bm[0], bm[1]);
                MMA16816(o[2*dg],   pam[g], bh[0], bh[1]);
                MMA16816(o[2*dg+1], pah[g], bh[2], bh[3]);
                MMA16816(o[2*dg+1], pah[g], bm[2], bm[3]);
                MMA16816(o[2*dg+1], pam[g], bh[2], bh[3]);
            }
        }
    }

    // epilogue: normalize, split hi/mid, store
    float li0 = 1.f / rl0, li1 = 1.f / rl1;
    int r = q0 + wid * 16 + (lane >> 2);
    __nv_bfloat16* goh = g_attn_hi  + (size_t)r * Q_SIZE + h * HD + (lane & 3) * 2;
    __nv_bfloat16* gom = g_attn_mid + (size_t)r * Q_SIZE + h * HD + (lane & 3) * 2;
#pragma unroll
    for (int nf = 0; nf < 16; nf++) {
        uint32_t h0, m0, h1, m1;
        split2(o[nf][0] * li0, o[nf][1] * li0, h0, m0);
        split2(o[nf][2] * li1, o[nf][3] * li1, h1, m1);
        *(uint32_t*)(goh + nf * 8)                      = h0;
        *(uint32_t*)(gom + nf * 8)                      = m0;
        *(uint32_t*)(goh + (size_t)8 * Q_SIZE + nf * 8) = h1;
        *(uint32_t*)(gom + (size_t)8 * Q_SIZE + nf * 8) = m1;
    }
}

// ---------------------------------------------------------------------------
extern "C" void kernel_launch(void* const* d_in, const int* in_sizes, int n_in,
                              void* d_out, int out_size) {
    const int*   positions = (const int*)d_in[0];
    const float* hidden    = (const float*)d_in[1];
    const float* lnw       = (const float*)d_in[2];
    const float* w_qkv     = (const float*)d_in[3];
    const float* w_o       = (const float*)d_in[4];
    float* out = (float*)d_out;

    void* p;
    cudaGetSymbolAddress(&p, g_qkv);      float* qkv = (float*)p;
    cudaGetSymbolAddress(&p, g_xn_hi);    __nv_bfloat16* xnh = (__nv_bfloat16*)p;
    cudaGetSymbolAddress(&p, g_xn_mid);   __nv_bfloat16* xnm = (__nv_bfloat16*)p;
    cudaGetSymbolAddress(&p, g_wqkv_hi);  __nv_bfloat16* wqh = (__nv_bfloat16*)p;
    cudaGetSymbolAddress(&p, g_wqkv_mid); __nv_bfloat16* wqm = (__nv_bfloat16*)p;
    cudaGetSymbolAddress(&p, g_wo_hi);    __nv_bfloat16* woh = (__nv_bfloat16*)p;
    cudaGetSymbolAddress(&p, g_wo_mid);   __nv_bfloat16* wom = (__nv_bfloat16*)p;
    cudaGetSymbolAddress(&p, g_attn_hi);  __nv_bfloat16* ath = (__nv_bfloat16*)p;
    cudaGetSymbolAddress(&p, g_attn_mid); __nv_bfloat16* atm = (__nv_bfloat16*)p;

    cudaFuncSetAttribute(gemm_mma_kernel, cudaFuncAttributeMaxDynamicSharedMemorySize, GEMM_SMEM);
    cudaFuncSetAttribute(flash_mma_kernel, cudaFuncAttributeMaxDynamicSharedMemorySize, FLASH_SMEM);

    // split weights to bf16 hi/mid
    split_kernel<<<(QKV_N * HID / 4 + 255) / 256, 256>>>(w_qkv, wqh, wqm, QKV_N * HID / 4);
    split_kernel<<<(Q_SIZE * HID / 4 + 255) / 256, 256>>>(w_o, woh, wom, Q_SIZE * HID / 4);

    // 1. RMSNorm -> xn hi/mid
    rmsnorm_kernel<<<S_LEN, 256>>>(hidden, lnw);

    // 2. QKV = xn @ w_qkv^T (HMMA split) -> fp32 g_qkv
    {
        dim3 grid(QKV_N / 128, S_LEN / 128);
        gemm_mma_kernel<<<grid, 256, GEMM_SMEM>>>(xnh, xnm, wqh, wqm, qkv, HID, QKV_N);
    }

    // 3. RoPE
    {
        dim3 grid(S_LEN, NQH + NKVH);
        rope_kernel<<<grid, 64>>>(positions);
    }

    // 4. Tensorized flash attention -> attn hi/mid
    {
        dim3 grid(S_LEN / 128, NQH);
        flash_mma_kernel<<<grid, 256, FLASH_SMEM>>>();
    }

    // 5. out = attn @ w_o^T (HMMA split) -> d_out fp32
    {
        dim3 grid(Q_SIZE / 128, S_LEN / 128);
        gemm_mma_kernel<<<grid, 256, GEMM_SMEM>>>(ath, atm, woh, wom, out, HID, Q_SIZE);
    }
    (void)in_sizes; (void)n_in; (void)out_size;
}

// round 13
// speedup vs baseline: 1.1234x; 1.1234x over previous
#include <cuda_runtime.h>
#include <cuda_bf16.h>
#include <math.h>
#include <stdint.h>

#define S_LEN 2048
#define HID   4096
#define NQH   32
#define NKVH  8
#define HD    128
#define QKV_N 6144
#define KV_OFF 4096
#define V_OFF  5120
#define Q_SIZE 4096

// ---------------- scratch (device globals, allocation-free) ----------------
__device__ float         g_qkv[S_LEN * QKV_N];
__device__ __nv_bfloat16 g_xn_hi[S_LEN * HID];
__device__ __nv_bfloat16 g_xn_mid[S_LEN * HID];
__device__ __nv_bfloat16 g_wqkv_hi[QKV_N * HID];
__device__ __nv_bfloat16 g_wqkv_mid[QKV_N * HID];
__device__ __nv_bfloat16 g_wo_hi[Q_SIZE * HID];
__device__ __nv_bfloat16 g_wo_mid[Q_SIZE * HID];
__device__ __nv_bfloat16 g_attn_hi[S_LEN * Q_SIZE];
__device__ __nv_bfloat16 g_attn_mid[S_LEN * Q_SIZE];
// pre-split attention operands
__device__ __nv_bfloat16 g_q_hi[S_LEN * Q_SIZE];
__device__ __nv_bfloat16 g_q_mid[S_LEN * Q_SIZE];
__device__ __nv_bfloat16 g_k_hi[NKVH * S_LEN * HD];
__device__ __nv_bfloat16 g_k_mid[NKVH * S_LEN * HD];
__device__ __nv_bfloat16 g_v_hi[NKVH * S_LEN * HD];
__device__ __nv_bfloat16 g_v_mid[NKVH * S_LEN * HD];

// ---------------- helpers ----------------
__device__ __forceinline__ uint32_t smem_u32(const void* p) {
    uint32_t a;
    asm("{ .reg .u64 t; cvta.to.shared.u64 t, %1; cvt.u32.u64 %0, t; }" : "=r"(a) : "l"(p));
    return a;
}
__device__ __forceinline__ void cp_async16(uint32_t dst, const void* src) {
    asm volatile("cp.async.cg.shared.global [%0], [%1], 16;" :: "r"(dst), "l"(src) : "memory");
}
__device__ __forceinline__ void cp_commit() { asm volatile("cp.async.commit_group;" ::: "memory"); }
__device__ __forceinline__ void cp_wait1() { asm volatile("cp.async.wait_group 1;" ::: "memory"); }
__device__ __forceinline__ void cp_wait0() { asm volatile("cp.async.wait_group 0;" ::: "memory"); }

#define LDSM4(r, addr)                                                             \
    asm volatile("ldmatrix.sync.aligned.m8n8.x4.shared.b16 {%0,%1,%2,%3}, [%4];"   \
        : "=r"((r)[0]), "=r"((r)[1]), "=r"((r)[2]), "=r"((r)[3]) : "r"(addr))

#define LDSM4T(r, addr)                                                                 \
    asm volatile("ldmatrix.sync.aligned.m8n8.x4.trans.shared.b16 {%0,%1,%2,%3}, [%4];"  \
        : "=r"((r)[0]), "=r"((r)[1]), "=r"((r)[2]), "=r"((r)[3]) : "r"(addr))

#define MMA16816(d, a, b0, b1)                                                     \
    asm volatile("mma.sync.aligned.m16n8k16.row.col.f32.bf16.bf16.f32 "            \
        "{%0,%1,%2,%3}, {%4,%5,%6,%7}, {%8,%9}, {%0,%1,%2,%3};"                    \
        : "+f"((d)[0]), "+f"((d)[1]), "+f"((d)[2]), "+f"((d)[3])                   \
        : "r"((a)[0]), "r"((a)[1]), "r"((a)[2]), "r"((a)[3]), "r"(b0), "r"(b1))

__device__ __forceinline__ void split2(float a, float b, uint32_t& hi, uint32_t& mid) {
    __nv_bfloat16 ha = __float2bfloat16(a), hb = __float2bfloat16(b);
    __nv_bfloat16 ma = __float2bfloat16(a - __bfloat162float(ha));
    __nv_bfloat16 mb = __float2bfloat16(b - __bfloat162float(hb));
    __nv_bfloat162 hv; hv.x = ha; hv.y = hb;
    __nv_bfloat162 mv; mv.x = ma; mv.y = mb;
    hi = *(uint32_t*)&hv; mid = *(uint32_t*)&mv;
}
__device__ __forceinline__ void split1(float a, __nv_bfloat16& h, __nv_bfloat16& m) {
    h = __float2bfloat16(a);
    m = __float2bfloat16(a - __bfloat162float(h));
}

// ---------------------------------------------------------------------------
// RMSNorm -> split bf16 (hi, mid)
// ---------------------------------------------------------------------------
__global__ __launch_bounds__(256) void rmsnorm_kernel(const float* __restrict__ x,
                                                      const float* __restrict__ w) {
    int row = blockIdx.x;
    int t = threadIdx.x;
    const float4* xr = (const float4*)(x + (size_t)row * HID);
    float4 v[4];
    float ss = 0.f;
#pragma unroll
    for (int i = 0; i < 4; i++) {
        v[i] = xr[t + i * 256];
        ss += v[i].x * v[i].x + v[i].y * v[i].y + v[i].z * v[i].z + v[i].w * v[i].w;
    }
    __shared__ float red[8];
#pragma unroll
    for (int o = 16; o > 0; o >>= 1) ss += __shfl_xor_sync(0xffffffffu, ss, o);
    if ((t & 31) == 0) red[t >> 5] = ss;
    __syncthreads();
    if (t < 8) {
        float s2 = red[t];
#pragma unroll
        for (int o = 4; o > 0; o >>= 1) s2 += __shfl_xor_sync(0xffu, s2, o);
        if (t == 0) red[0] = s2;
    }
    __syncthreads();
    float inv = rsqrtf(red[0] / (float)HID + 1e-5f);
    const float4* wr = (const float4*)w;
    __nv_bfloat16* oh = g_xn_hi + (size_t)row * HID;
    __nv_bfloat16* om = g_xn_mid + (size_t)row * HID;
#pragma unroll
    for (int i = 0; i < 4; i++) {
        float4 wv = wr[t + i * 256];
        float f[4];
        f[0] = v[i].x * inv * wv.x; f[1] = v[i].y * inv * wv.y;
        f[2] = v[i].z * inv * wv.z; f[3] = v[i].w * inv * wv.w;
        int base = (t + i * 256) * 4;
        uint32_t h0, m0, h1, m1;
        split2(f[0], f[1], h0, m0);
        split2(f[2], f[3], h1, m1);
        *(uint32_t*)(oh + base)     = h0;
        *(uint32_t*)(oh + base + 2) = h1;
        *(uint32_t*)(om + base)     = m0;
        *(uint32_t*)(om + base + 2) = m1;
    }
}

// ---------------------------------------------------------------------------
// fp32 -> (hi, mid) bf16 split
// ---------------------------------------------------------------------------
__global__ __launch_bounds__(256) void split_kernel(const float* __restrict__ s,
                                                    __nv_bfloat16* __restrict__ hi,
                                                    __nv_bfloat16* __restrict__ mid, int n4) {
    int i = blockIdx.x * 256 + threadIdx.x;
    if (i >= n4) return;
    float4 v = ((const float4*)s)[i];
    uint32_t h0, m0, h1, m1;
    split2(v.x, v.y, h0, m0);
    split2(v.z, v.w, h1, m1);
    *(uint32_t*)(hi + i*4)      = h0;
    *(uint32_t*)(hi + i*4 + 2)  = h1;
    *(uint32_t*)(mid + i*4)     = m0;
    *(uint32_t*)(mid + i*4 + 2) = m1;
}

// ---------------------------------------------------------------------------
// mma.sync bf16-split GEMM (R11 proven config: 2-stage, 2 CTAs/SM)
// ---------------------------------------------------------------------------
#define GK   32
#define TSTR 80
#define TILE_B (128 * TSTR)
#define STAGE_B (4 * TILE_B)
#define GEMM_SMEM (2 * STAGE_B)

__global__ __launch_bounds__(256) void gemm_mma_kernel(
    const __nv_bfloat16* __restrict__ Ah, const __nv_bfloat16* __restrict__ Am,
    const __nv_bfloat16* __restrict__ Bh, const __nv_bfloat16* __restrict__ Bm,
    float* __restrict__ C, int K, int N)
{
    extern __shared__ char smem[];
    int t = threadIdx.x;
    int lane = t & 31, warp = t >> 5;
    int wm = warp & 3, wn = warp >> 2;
    int m0 = blockIdx.y * 128, n0 = blockIdx.x * 128;

    const __nv_bfloat16* gsrc[4] = { Ah + (size_t)m0 * K, Am + (size_t)m0 * K,
                                     Bh + (size_t)n0 * K, Bm + (size_t)n0 * K };
    uint32_t sbase = smem_u32(smem);
    int lr = t >> 2, lseg = t & 3;

    float acc[2][8][4];
#pragma unroll
    for (int i = 0; i < 2; i++)
#pragma unroll
        for (int j = 0; j < 8; j++)
#pragma unroll
            for (int q = 0; q < 4; q++) acc[i][j][q] = 0.f;

    int NC = K / GK;
    {
#pragma unroll
        for (int mt = 0; mt < 4; mt++) {
            const __nv_bfloat16* g = gsrc[mt] + (size_t)lr * K + lseg * 8;
            uint32_t d = sbase + mt * TILE_B + lr * TSTR + lseg * 16;
            cp_async16(d, g);
            cp_async16(d + 64 * TSTR, g + (size_t)64 * K);
        }
        cp_commit();
    }

    for (int c = 0; c < NC; c++) {
        int s = c & 1;
        if (c + 1 < NC) {
            int kc = (c + 1) * GK;
#pragma unroll
            for (int mt = 0; mt < 4; mt++) {
                const __nv_bfloat16* g = gsrc[mt] + (size_t)lr * K + kc + lseg * 8;
                uint32_t d = sbase + (s ^ 1) * STAGE_B + mt * TILE_B + lr * TSTR + lseg * 16;
                cp_async16(d, g);
                cp_async16(d + 64 * TSTR, g + (size_t)64 * K);
            }
            cp_commit();
            cp_wait1();
        } else {
            cp_wait0();
        }
        __syncthreads();

        uint32_t st = sbase + s * STAGE_B;
#pragma unroll
        for (int kk = 0; kk < 2; kk++) {
            uint32_t a_hi[2][4], a_mi[2][4];
            int kbA = kk * 32 + ((lane >> 4) << 4);
#pragma unroll
            for (int mf = 0; mf < 2; mf++) {
                uint32_t addr = st + (uint32_t)(wm * 32 + mf * 16 + (lane & 15)) * TSTR + kbA;
                LDSM4(a_hi[mf], addr);
                LDSM4(a_mi[mf], addr + TILE_B);
            }
            uint32_t b_hi[4][4], b_mi[4][4];
            int q = lane >> 3;
            int nbase = wn * 64 + ((q & 2) << 2) + (lane & 7);
            int kbB = kk * 32 + ((q & 1) << 4);
#pragma unroll
            for (int g = 0; g < 4; g++) {
                uint32_t addr = st + 2 * TILE_B + (uint32_t)(nbase + g * 16) * TSTR + kbB;
                LDSM4(b_hi[g], addr);
                LDSM4(b_mi[g], addr + TILE_B);
            }
#pragma unroll
            for (int mf = 0; mf < 2; mf++) {
#pragma unroll
                for (int nf = 0; nf < 8; nf++) {
                    int g = nf >> 1, j = (nf & 1) * 2;
                    MMA16816(acc[mf][nf], a_hi[mf], b_hi[g][j], b_hi[g][j + 1]);
                    MMA16816(acc[mf][nf], a_hi[mf], b_mi[g][j], b_mi[g][j + 1]);
                    MMA16816(acc[mf][nf], a_mi[mf], b_hi[g][j], b_hi[g][j + 1]);
                }
            }
        }
        __syncthreads();
    }

#pragma unroll
    for (int mf = 0; mf < 2; mf++) {
#pragma unroll
        for (int nf = 0; nf < 8; nf++) {
            int r = m0 + wm * 32 + mf * 16 + (lane >> 2);
            int cc = n0 + wn * 64 + nf * 8 + (lane & 3) * 2;
            *(float2*)&C[(size_t)r * N + cc]       = make_float2(acc[mf][nf][0], acc[mf][nf][1]);
            *(float2*)&C[(size_t)(r + 8) * N + cc] = make_float2(acc[mf][nf][2], acc[mf][nf][3]);
        }
    }
}

// ---------------------------------------------------------------------------
// RoPE + pre-split of Q (scaled), K, V into bf16 hi/mid gmem arrays
// grid (S_LEN, 48): h<32 Q, 32..39 K, 40..47 V
// ---------------------------------------------------------------------------
__global__ __launch_bounds__(64) void rope_split_kernel(const int* __restrict__ positions) {
    int s = blockIdx.x;
    int h = blockIdx.y;
    int d = threadIdx.x;
    const float scale = 0.08838834764831845f;

    if (h < NQH) {
        float pos = (float)positions[s];
        float invf = powf(10000.0f, -((float)(2 * d)) / 128.0f);
        float f = pos * invf;
        float c = cosf(f), sn = sinf(f);
        const float* base = g_qkv + (size_t)s * QKV_N + h * HD;
        float x1 = base[d], x2 = base[d + 64];
        float y1 = (x1 * c - x2 * sn) * scale;
        float y2 = (x2 * c + x1 * sn) * scale;
        size_t o = (size_t)s * Q_SIZE + h * HD;
        __nv_bfloat16 hh, mm;
        split1(y1, hh, mm); g_q_hi[o + d] = hh;      g_q_mid[o + d] = mm;
        split1(y2, hh, mm); g_q_hi[o + d + 64] = hh; g_q_mid[o + d + 64] = mm;
    } else if (h < NQH + NKVH) {
        int kh = h - NQH;
        float pos = (float)positions[s];
        float invf = powf(10000.0f, -((float)(2 * d)) / 128.0f);
        float f = pos * invf;
        float c = cosf(f), sn = sinf(f);
        const float* base = g_qkv + (size_t)s * QKV_N + KV_OFF + kh * HD;
        float x1 = base[d], x2 = base[d + 64];
        float y1 = x1 * c - x2 * sn;
        float y2 = x2 * c + x1 * sn;
        size_t o = ((size_t)kh * S_LEN + s) * HD;
        __nv_bfloat16 hh, mm;
        split1(y1, hh, mm); g_k_hi[o + d] = hh;      g_k_mid[o + d] = mm;
        split1(y2, hh, mm); g_k_hi[o + d + 64] = hh; g_k_mid[o + d + 64] = mm;
    } else {
        int vh = h - NQH - NKVH;
        const float* base = g_qkv + (size_t)s * QKV_N + V_OFF + vh * HD;
        size_t o = ((size_t)vh * S_LEN + s) * HD;
        __nv_bfloat16 hh, mm;
        split1(base[d], hh, mm);      g_v_hi[o + d] = hh;      g_v_mid[o + d] = mm;
        split1(base[d + 64], hh, mm); g_v_hi[o + d + 64] = hh; g_v_mid[o + d + 64] = mm;
    }
}

// ---------------------------------------------------------------------------
// Tensorized flash attention, pre-split bf16 operands, 2-stage cp.async KV.
// smem: Qhi|Qmid (2*FQ_B) + 2 stages of [Khi|Kmid|Vhi|Vmid] (4*FK_B each).
// ---------------------------------------------------------------------------
#define FSTR 272
#define FQ_B  (128 * FSTR)            // 34816
#define FK_B  (64 * FSTR)             // 17408
#define KVSTAGE_B (4 * FK_B)          // 69632
#define FLASH_SMEM (2 * FQ_B + 2 * KVSTAGE_B)   // 208896

__device__ __forceinline__ void flash_issue_kv(uint32_t dstbase, int kvh, int n0, int t) {
    const __nv_bfloat16* s0 = g_k_hi  + ((size_t)kvh * S_LEN + n0) * HD;
    const __nv_bfloat16* s1 = g_k_mid + ((size_t)kvh * S_LEN + n0) * HD;
    const __nv_bfloat16* s2 = g_v_hi  + ((size_t)kvh * S_LEN + n0) * HD;
    const __nv_bfloat16* s3 = g_v_mid + ((size_t)kvh * S_LEN + n0) * HD;
    const __nv_bfloat16* srcs[4] = {s0, s1, s2, s3};
#pragma unroll
    for (int i = 0; i < 16; i++) {
        int idx = t + i * 256;          // 4096 chunks of 16B
        int arr = idx >> 10;
        int within = idx & 1023;
        int r = within >> 4, c = within & 15;
        cp_async16(dstbase + arr * FK_B + (uint32_t)r * FSTR + c * 16,
                   srcs[arr] + (size_t)r * HD + c * 8);
    }
}

__global__ __launch_bounds__(256) void flash_mma_kernel() {
    extern __shared__ char fsm[];
    uint32_t uQ  = smem_u32(fsm);
    uint32_t uKV = uQ + 2 * FQ_B;

    int qt = 15 - (int)blockIdx.x;        // heavy tiles first
    int h  = blockIdx.y;
    int kvh = h >> 2;
    int t = threadIdx.x;
    int lane = t & 31, wid = t >> 5;
    int q0 = qt * 128;

    // issue Q (hi+mid) + KV stage 0, one commit group
    {
        const __nv_bfloat16* qh = g_q_hi  + (size_t)q0 * Q_SIZE + h * HD;
        const __nv_bfloat16* qm = g_q_mid + (size_t)q0 * Q_SIZE + h * HD;
#pragma unroll
        for (int i = 0; i < 16; i++) {
            int idx = t + i * 256;         // 4096 chunks: [hi 2048][mid 2048]
            int arr = idx >> 11;
            int within = idx & 2047;
            int r = within >> 4, c = within & 15;
            const __nv_bfloat16* src = (arr == 0 ? qh : qm) + (size_t)r * Q_SIZE + c * 8;
            cp_async16(uQ + arr * FQ_B + (uint32_t)r * FSTR + c * 16, src);
        }
        flash_issue_kv(uKV, kvh, 0, t);
        cp_commit();
    }

    float rm0 = -1e30f, rm1 = -1e30f, rl0 = 0.f, rl1 = 0.f;
    float o[16][4];
#pragma unroll
    for (int i = 0; i < 16; i++)
#pragma unroll
        for (int j = 0; j < 4; j++) o[i][j] = 0.f;

    int ktmax = 2 * qt + 1;
    for (int kt = 0; kt <= ktmax; kt++) {
        int n0 = kt * 64;
        if (kt + 1 <= ktmax) {
            flash_issue_kv(uKV + ((kt + 1) & 1) * KVSTAGE_B, kvh, (kt + 1) * 64, t);
            cp_commit();
            cp_wait1();
        } else {
            cp_wait0();
        }
        __syncthreads();

        uint32_t uK = uKV + (kt & 1) * KVSTAGE_B;   // K hi
        uint32_t uV = uK + 2 * FK_B;                // V hi

        // S = Q K^T  (warp: m16 x n64)
        float s[8][4];
#pragma unroll
        for (int i = 0; i < 8; i++)
#pragma unroll
            for (int j = 0; j < 4; j++) s[i][j] = 0.f;

        int q = lane >> 3;
        uint32_t brow = ((q & 2) << 2) + (lane & 7);
        uint32_t bko  = (uint32_t)((q & 1) << 4);
#pragma unroll
        for (int kc = 0; kc < 8; kc++) {
            uint32_t ah[4], am[4];
            uint32_t aaddr = uQ + (uint32_t)(wid * 16 + (lane & 15)) * FSTR + kc * 32 + ((lane >> 4) << 4);
            LDSM4(ah, aaddr);
            LDSM4(am, aaddr + FQ_B);
#pragma unroll
            for (int g = 0; g < 4; g++) {
                uint32_t bh[4], bm[4];
                uint32_t baddr = uK + (uint32_t)(g * 16 + brow) * FSTR + kc * 32 + bko;
                LDSM4(bh, baddr);
                LDSM4(bm, baddr + FK_B);
                MMA16816(s[2*g],   ah, bh[0], bh[1]);
                MMA16816(s[2*g],   ah, bm[0], bm[1]);
                MMA16816(s[2*g],   am, bh[0], bh[1]);
                MMA16816(s[2*g+1], ah, bh[2], bh[3]);
                MMA16816(s[2*g+1], ah, bm[2], bm[3]);
                MMA16816(s[2*g+1], am, bh[2], bh[3]);
            }
        }

        int r0g = q0 + wid * 16 + (lane >> 2);
        if (kt >= 2 * qt) {
#pragma unroll
            for (int nf = 0; nf < 8; nf++) {
                int c0 = n0 + nf * 8 + (lane & 3) * 2;
                if (c0     > r0g)     s[nf][0] = -1e30f;
                if (c0 + 1 > r0g)     s[nf][1] = -1e30f;
                if (c0     > r0g + 8) s[nf][2] = -1e30f;
                if (c0 + 1 > r0g + 8) s[nf][3] = -1e30f;
            }
        }
        float mx0 = -1e30f, mx1 = -1e30f;
#pragma unroll
        for (int nf = 0; nf < 8; nf++) {
            mx0 = fmaxf(mx0, fmaxf(s[nf][0], s[nf][1]));
            mx1 = fmaxf(mx1, fmaxf(s[nf][2], s[nf][3]));
        }
        mx0 = fmaxf(mx0, __shfl_xor_sync(0xffffffffu, mx0, 1));
        mx0 = fmaxf(mx0, __shfl_xor_sync(0xffffffffu, mx0, 2));
        mx1 = fmaxf(mx1, __shfl_xor_sync(0xffffffffu, mx1, 1));
        mx1 = fmaxf(mx1, __shfl_xor_sync(0xffffffffu, mx1, 2));
        float mn0 = fmaxf(rm0, mx0), mn1 = fmaxf(rm1, mx1);
        float cr0 = __expf(rm0 - mn0), cr1 = __expf(rm1 - mn1);
        rm0 = mn0; rm1 = mn1;

        uint32_t pah[4][4], pam[4][4];
        float ls0 = 0.f, ls1 = 0.f;
#pragma unroll
        for (int g = 0; g < 4; g++) {
            float pA0 = __expf(s[2*g][0]   - mn0), pA1 = __expf(s[2*g][1]   - mn0);
            float pA2 = __expf(s[2*g][2]   - mn1), pA3 = __expf(s[2*g][3]   - mn1);
            float pB0 = __expf(s[2*g+1][0] - mn0), pB1 = __expf(s[2*g+1][1] - mn0);
            float pB2 = __expf(s[2*g+1][2] - mn1), pB3 = __expf(s[2*g+1][3] - mn1);
            ls0 += pA0 + pA1 + pB0 + pB1;
            ls1 += pA2 + pA3 + pB2 + pB3;
            split2(pA0, pA1, pah[g][0], pam[g][0]);
            split2(pA2, pA3, pah[g][1], pam[g][1]);
            split2(pB0, pB1, pah[g][2], pam[g][2]);
            split2(pB2, pB3, pah[g][3], pam[g][3]);
        }
        ls0 += __shfl_xor_sync(0xffffffffu, ls0, 1);
        ls0 += __shfl_xor_sync(0xffffffffu, ls0, 2);
        ls1 += __shfl_xor_sync(0xffffffffu, ls1, 1);
        ls1 += __shfl_xor_sync(0xffffffffu, ls1, 2);
        rl0 = rl0 * cr0 + ls0;
        rl1 = rl1 * cr1 + ls1;

#pragma unroll
        for (int nf = 0; nf < 16; nf++) {
            o[nf][0] *= cr0; o[nf][1] *= cr0;
            o[nf][2] *= cr1; o[nf][3] *= cr1;
        }

        // O += P V   (B frags via ldmatrix.trans on V[kv][d])
#pragma unroll
        for (int g = 0; g < 4; g++) {
#pragma unroll
            for (int dg = 0; dg < 8; dg++) {
                uint32_t bh[4], bm[4];
                uint32_t vaddr = uV + (uint32_t)(g * 16 + (lane & 15)) * FSTR + dg * 32 + ((lane >> 4) << 4);
                LDSM4T(bh, vaddr);
                LDSM4T(bm, vaddr + FK_B);
                MMA16816(o[2*dg],   pah[g], bh[0], bh[1]);
                MMA16816(o[2*dg],   pah[g], bm[0], bm[1]);
                MMA16816(o[2*dg],   pam[g], bh[0], bh[1]);
                MMA16816(o[2*dg+1], pah[g], bh[2], bh[3]);
                MMA16816(o[2*dg+1], pah[g], bm[2], bm[3]);
                MMA16816(o[2*dg+1], pam[g], bh[2], bh[3]);
            }
        }
        __syncthreads();   // reads of this stage done before its buffer is re-issued
    }

    // epilogue: normalize, split hi/mid, store
    float li0 = 1.f / rl0, li1 = 1.f / rl1;
    int r = q0 + wid * 16 + (lane >> 2);
    __nv_bfloat16* goh = g_attn_hi  + (size_t)r * Q_SIZE + h * HD + (lane & 3) * 2;
    __nv_bfloat16* gom = g_attn_mid + (size_t)r * Q_SIZE + h * HD + (lane & 3) * 2;
#pragma unroll
    for (int nf = 0; nf < 16; nf++) {
        uint32_t h0, m0, h1, m1;
        split2(o[nf][0] * li0, o[nf][1] * li0, h0, m0);
        split2(o[nf][2] * li1, o[nf][3] * li1, h1, m1);
        *(uint32_t*)(goh + nf * 8)                      = h0;
        *(uint32_t*)(gom + nf * 8)                      = m0;
        *(uint32_t*)(goh + (size_t)8 * Q_SIZE + nf * 8) = h1;
        *(uint32_t*)(gom + (size_t)8 * Q_SIZE + nf * 8) = m1;
    }
}

// ---------------------------------------------------------------------------
extern "C" void kernel_launch(void* const* d_in, const int* in_sizes, int n_in,
                              void* d_out, int out_size) {
    const int*   positions = (const int*)d_in[0];
    const float* hidden    = (const float*)d_in[1];
    const float* lnw       = (const float*)d_in[2];
    const float* w_qkv     = (const float*)d_in[3];
    const float* w_o       = (const float*)d_in[4];
    float* out = (float*)d_out;

    void* p;
    cudaGetSymbolAddress(&p, g_qkv);      float* qkv = (float*)p;
    cudaGetSymbolAddress(&p, g_xn_hi);    __nv_bfloat16* xnh = (__nv_bfloat16*)p;
    cudaGetSymbolAddress(&p, g_xn_mid);   __nv_bfloat16* xnm = (__nv_bfloat16*)p;
    cudaGetSymbolAddress(&p, g_wqkv_hi);  __nv_bfloat16* wqh = (__nv_bfloat16*)p;
    cudaGetSymbolAddress(&p, g_wqkv_mid); __nv_bfloat16* wqm = (__nv_bfloat16*)p;
    cudaGetSymbolAddress(&p, g_wo_hi);    __nv_bfloat16* woh = (__nv_bfloat16*)p;
    cudaGetSymbolAddress(&p, g_wo_mid);   __nv_bfloat16* wom = (__nv_bfloat16*)p;
    cudaGetSymbolAddress(&p, g_attn_hi);  __nv_bfloat16* ath = (__nv_bfloat16*)p;
    cudaGetSymbolAddress(&p, g_attn_mid); __nv_bfloat16* atm = (__nv_bfloat16*)p;

    cudaFuncSetAttribute(gemm_mma_kernel, cudaFuncAttributeMaxDynamicSharedMemorySize, GEMM_SMEM);
    cudaFuncSetAttribute(flash_mma_kernel, cudaFuncAttributeMaxDynamicSharedMemorySize, FLASH_SMEM);

    // split weights to bf16 hi/mid
    split_kernel<<<(QKV_N * HID / 4 + 255) / 256, 256>>>(w_qkv, wqh, wqm, QKV_N * HID / 4);
    split_kernel<<<(Q_SIZE * HID / 4 + 255) / 256, 256>>>(w_o, woh, wom, Q_SIZE * HID / 4);

    // 1. RMSNorm -> xn hi/mid
    rmsnorm_kernel<<<S_LEN, 256>>>(hidden, lnw);

    // 2. QKV = xn @ w_qkv^T (HMMA split) -> fp32 g_qkv
    {
        dim3 grid(QKV_N / 128, S_LEN / 128);
        gemm_mma_kernel<<<grid, 256, GEMM_SMEM>>>(xnh, xnm, wqh, wqm, qkv, HID, QKV_N);
    }

    // 3. RoPE + pre-split Q(scaled)/K/V to bf16 hi/mid
    {
        dim3 grid(S_LEN, NQH + 2 * NKVH);
        rope_split_kernel<<<grid, 64>>>(positions);
    }

    // 4. Tensorized flash attention (pipelined bf16 loads) -> attn hi/mid
    {
        dim3 grid(S_LEN / 128, NQH);
        flash_mma_kernel<<<grid, 256, FLASH_SMEM>>>();
    }

    // 5. out = attn @ w_o^T (HMMA split) -> d_out fp32
    {
        dim3 grid(Q_SIZE / 128, S_LEN / 128);
        gemm_mma_kernel<<<grid, 256, GEMM_SMEM>>>(ath, atm, woh, wom, out, HID, Q_SIZE);
    }
    (void)in_sizes; (void)n_in; (void)out_size;
}

// round 14
// speedup vs baseline: 1.1267x; 1.0029x over previous
#include <cuda_runtime.h>
#include <cuda_bf16.h>
#include <math.h>
#include <stdint.h>

#define S_LEN 2048
#define HID   4096
#define NQH   32
#define NKVH  8
#define HD    128
#define QKV_N 6144
#define Q_SIZE 4096

// ---------------- scratch (device globals, allocation-free) ----------------
__device__ __nv_bfloat16 g_xn_hi[S_LEN * HID];
__device__ __nv_bfloat16 g_xn_mid[S_LEN * HID];
__device__ __nv_bfloat16 g_wqkv_hi[QKV_N * HID];
__device__ __nv_bfloat16 g_wqkv_mid[QKV_N * HID];
__device__ __nv_bfloat16 g_wo_hi[Q_SIZE * HID];
__device__ __nv_bfloat16 g_wo_mid[Q_SIZE * HID];
__device__ __nv_bfloat16 g_attn_hi[S_LEN * Q_SIZE];
__device__ __nv_bfloat16 g_attn_mid[S_LEN * Q_SIZE];
// pre-split attention operands
__device__ __nv_bfloat16 g_q_hi[S_LEN * Q_SIZE];
__device__ __nv_bfloat16 g_q_mid[S_LEN * Q_SIZE];
__device__ __nv_bfloat16 g_k_hi[NKVH * S_LEN * HD];
__device__ __nv_bfloat16 g_k_mid[NKVH * S_LEN * HD];
__device__ __nv_bfloat16 g_v_hi[NKVH * S_LEN * HD];
__device__ __nv_bfloat16 g_v_mid[NKVH * S_LEN * HD];

// ---------------- helpers ----------------
__device__ __forceinline__ uint32_t smem_u32(const void* p) {
    uint32_t a;
    asm("{ .reg .u64 t; cvta.to.shared.u64 t, %1; cvt.u32.u64 %0, t; }" : "=r"(a) : "l"(p));
    return a;
}
__device__ __forceinline__ void cp_async16(uint32_t dst, const void* src) {
    asm volatile("cp.async.cg.shared.global [%0], [%1], 16;" :: "r"(dst), "l"(src) : "memory");
}
__device__ __forceinline__ void cp_commit() { asm volatile("cp.async.commit_group;" ::: "memory"); }
__device__ __forceinline__ void cp_wait1() { asm volatile("cp.async.wait_group 1;" ::: "memory"); }
__device__ __forceinline__ void cp_wait0() { asm volatile("cp.async.wait_group 0;" ::: "memory"); }

#define LDSM4(r, addr)                                                             \
    asm volatile("ldmatrix.sync.aligned.m8n8.x4.shared.b16 {%0,%1,%2,%3}, [%4];"   \
        : "=r"((r)[0]), "=r"((r)[1]), "=r"((r)[2]), "=r"((r)[3]) : "r"(addr))

#define LDSM4T(r, addr)                                                                 \
    asm volatile("ldmatrix.sync.aligned.m8n8.x4.trans.shared.b16 {%0,%1,%2,%3}, [%4];"  \
        : "=r"((r)[0]), "=r"((r)[1]), "=r"((r)[2]), "=r"((r)[3]) : "r"(addr))

#define MMA16816(d, a, b0, b1)                                                     \
    asm volatile("mma.sync.aligned.m16n8k16.row.col.f32.bf16.bf16.f32 "            \
        "{%0,%1,%2,%3}, {%4,%5,%6,%7}, {%8,%9}, {%0,%1,%2,%3};"                    \
        : "+f"((d)[0]), "+f"((d)[1]), "+f"((d)[2]), "+f"((d)[3])                   \
        : "r"((a)[0]), "r"((a)[1]), "r"((a)[2]), "r"((a)[3]), "r"(b0), "r"(b1))

__device__ __forceinline__ void split2(float a, float b, uint32_t& hi, uint32_t& mid) {
    __nv_bfloat16 ha = __float2bfloat16(a), hb = __float2bfloat16(b);
    __nv_bfloat16 ma = __float2bfloat16(a - __bfloat162float(ha));
    __nv_bfloat16 mb = __float2bfloat16(b - __bfloat162float(hb));
    __nv_bfloat162 hv; hv.x = ha; hv.y = hb;
    __nv_bfloat162 mv; mv.x = ma; mv.y = mb;
    hi = *(uint32_t*)&hv; mid = *(uint32_t*)&mv;
}

// ---------------------------------------------------------------------------
// RMSNorm -> split bf16 (hi, mid)
// ---------------------------------------------------------------------------
__global__ __launch_bounds__(256) void rmsnorm_kernel(const float* __restrict__ x,
                                                      const float* __restrict__ w) {
    int row = blockIdx.x;
    int t = threadIdx.x;
    const float4* xr = (const float4*)(x + (size_t)row * HID);
    float4 v[4];
    float ss = 0.f;
#pragma unroll
    for (int i = 0; i < 4; i++) {
        v[i] = xr[t + i * 256];
        ss += v[i].x * v[i].x + v[i].y * v[i].y + v[i].z * v[i].z + v[i].w * v[i].w;
    }
    __shared__ float red[8];
#pragma unroll
    for (int o = 16; o > 0; o >>= 1) ss += __shfl_xor_sync(0xffffffffu, ss, o);
    if ((t & 31) == 0) red[t >> 5] = ss;
    __syncthreads();
    if (t < 8) {
        float s2 = red[t];
#pragma unroll
        for (int o = 4; o > 0; o >>= 1) s2 += __shfl_xor_sync(0xffu, s2, o);
        if (t == 0) red[0] = s2;
    }
    __syncthreads();
    float inv = rsqrtf(red[0] / (float)HID + 1e-5f);
    const float4* wr = (const float4*)w;
    __nv_bfloat16* oh = g_xn_hi + (size_t)row * HID;
    __nv_bfloat16* om = g_xn_mid + (size_t)row * HID;
#pragma unroll
    for (int i = 0; i < 4; i++) {
        float4 wv = wr[t + i * 256];
        float f[4];
        f[0] = v[i].x * inv * wv.x; f[1] = v[i].y * inv * wv.y;
        f[2] = v[i].z * inv * wv.z; f[3] = v[i].w * inv * wv.w;
        int base = (t + i * 256) * 4;
        uint32_t h0, m0, h1, m1;
        split2(f[0], f[1], h0, m0);
        split2(f[2], f[3], h1, m1);
        *(uint32_t*)(oh + base)     = h0;
        *(uint32_t*)(oh + base + 2) = h1;
        *(uint32_t*)(om + base)     = m0;
        *(uint32_t*)(om + base + 2) = m1;
    }
}

// ---------------------------------------------------------------------------
// fp32 -> (hi, mid) bf16 split
// ---------------------------------------------------------------------------
__global__ __launch_bounds__(256) void split_kernel(const float* __restrict__ s,
                                                    __nv_bfloat16* __restrict__ hi,
                                                    __nv_bfloat16* __restrict__ mid, int n4) {
    int i = blockIdx.x * 256 + threadIdx.x;
    if (i >= n4) return;
    float4 v = ((const float4*)s)[i];
    uint32_t h0, m0, h1, m1;
    split2(v.x, v.y, h0, m0);
    split2(v.z, v.w, h1, m1);
    *(uint32_t*)(hi + i*4)      = h0;
    *(uint32_t*)(hi + i*4 + 2)  = h1;
    *(uint32_t*)(mid + i*4)     = m0;
    *(uint32_t*)(mid + i*4 + 2) = m1;
}

// ---------------------------------------------------------------------------
// mma.sync bf16-split GEMM (R11 proven core: 2-stage, 2 CTAs/SM).
// mode 0: fp32 C store (O-proj). mode 1: fused RoPE+scale+split epilogue (QKV).
// ---------------------------------------------------------------------------
#define GK   32
#define TSTR 80
#define TILE_B (128 * TSTR)
#define STAGE_B (4 * TILE_B)
#define GEMM_SMEM (2 * STAGE_B)

__global__ __launch_bounds__(256, 2) void gemm_mma_kernel(
    const __nv_bfloat16* __restrict__ Ah, const __nv_bfloat16* __restrict__ Am,
    const __nv_bfloat16* __restrict__ Bh, const __nv_bfloat16* __restrict__ Bm,
    float* __restrict__ C, int K, int N, int mode,
    const int* __restrict__ positions)
{
    extern __shared__ char smem[];
    int t = threadIdx.x;
    int lane = t & 31, warp = t >> 5;
    int wm = warp & 3, wn = warp >> 2;
    int m0 = blockIdx.y * 128, n0 = blockIdx.x * 128;

    const __nv_bfloat16* gsrc[4] = { Ah + (size_t)m0 * K, Am + (size_t)m0 * K,
                                     Bh + (size_t)n0 * K, Bm + (size_t)n0 * K };
    uint32_t sbase = smem_u32(smem);
    int lr = t >> 2, lseg = t & 3;

    float acc[2][8][4];
#pragma unroll
    for (int i = 0; i < 2; i++)
#pragma unroll
        for (int j = 0; j < 8; j++)
#pragma unroll
            for (int q = 0; q < 4; q++) acc[i][j][q] = 0.f;

    int NC = K / GK;
    {
#pragma unroll
        for (int mt = 0; mt < 4; mt++) {
            const __nv_bfloat16* g = gsrc[mt] + (size_t)lr * K + lseg * 8;
            uint32_t d = sbase + mt * TILE_B + lr * TSTR + lseg * 16;
            cp_async16(d, g);
            cp_async16(d + 64 * TSTR, g + (size_t)64 * K);
        }
        cp_commit();
    }

    for (int c = 0; c < NC; c++) {
        int s = c & 1;
        if (c + 1 < NC) {
            int kc = (c + 1) * GK;
#pragma unroll
            for (int mt = 0; mt < 4; mt++) {
                const __nv_bfloat16* g = gsrc[mt] + (size_t)lr * K + kc + lseg * 8;
                uint32_t d = sbase + (s ^ 1) * STAGE_B + mt * TILE_B + lr * TSTR + lseg * 16;
                cp_async16(d, g);
                cp_async16(d + 64 * TSTR, g + (size_t)64 * K);
            }
            cp_commit();
            cp_wait1();
        } else {
            cp_wait0();
        }
        __syncthreads();

        uint32_t st = sbase + s * STAGE_B;
#pragma unroll
        for (int kk = 0; kk < 2; kk++) {
            uint32_t a_hi[2][4], a_mi[2][4];
            int kbA = kk * 32 + ((lane >> 4) << 4);
#pragma unroll
            for (int mf = 0; mf < 2; mf++) {
                uint32_t addr = st + (uint32_t)(wm * 32 + mf * 16 + (lane & 15)) * TSTR + kbA;
                LDSM4(a_hi[mf], addr);
                LDSM4(a_mi[mf], addr + TILE_B);
            }
            uint32_t b_hi[4][4], b_mi[4][4];
            int q = lane >> 3;
            int nbase = wn * 64 + ((q & 2) << 2) + (lane & 7);
            int kbB = kk * 32 + ((q & 1) << 4);
#pragma unroll
            for (int g = 0; g < 4; g++) {
                uint32_t addr = st + 2 * TILE_B + (uint32_t)(nbase + g * 16) * TSTR + kbB;
                LDSM4(b_hi[g], addr);
                LDSM4(b_mi[g], addr + TILE_B);
            }
#pragma unroll
            for (int mf = 0; mf < 2; mf++) {
#pragma unroll
                for (int nf = 0; nf < 8; nf++) {
                    int g = nf >> 1, j = (nf & 1) * 2;
                    MMA16816(acc[mf][nf], a_hi[mf], b_hi[g][j], b_hi[g][j + 1]);
                    MMA16816(acc[mf][nf], a_hi[mf], b_mi[g][j], b_mi[g][j + 1]);
                    MMA16816(acc[mf][nf], a_mi[mf], b_hi[g][j], b_hi[g][j + 1]);
                }
            }
        }
        __syncthreads();
    }

    if (mode == 0) {
#pragma unroll
        for (int mf = 0; mf < 2; mf++) {
#pragma unroll
            for (int nf = 0; nf < 8; nf++) {
                int r = m0 + wm * 32 + mf * 16 + (lane >> 2);
                int cc = n0 + wn * 64 + nf * 8 + (lane & 3) * 2;
                *(float2*)&C[(size_t)r * N + cc]       = make_float2(acc[mf][nf][0], acc[mf][nf][1]);
                *(float2*)&C[(size_t)(r + 8) * N + cc] = make_float2(acc[mf][nf][2], acc[mf][nf][3]);
            }
        }
        return;
    }

    // ---- mode 1: fused RoPE + scale + hi/mid split epilogue (QKV) ----
    float* sf = (float*)smem;   // 128 x 132 fp32 tile (67.6 KB)
#pragma unroll
    for (int mf = 0; mf < 2; mf++) {
#pragma unroll
        for (int nf = 0; nf < 8; nf++) {
            int r = wm * 32 + mf * 16 + (lane >> 2);
            int cc = wn * 64 + nf * 8 + (lane & 3) * 2;
            *(float2*)&sf[r * 132 + cc]       = make_float2(acc[mf][nf][0], acc[mf][nf][1]);
            *(float2*)&sf[(r + 8) * 132 + cc] = make_float2(acc[mf][nf][2], acc[mf][nf][3]);
        }
    }
    __syncthreads();

    int hq = n0 >> 7;   // 0..31 Q, 32..39 K, 40..47 V
    const float qscale = 0.08838834764831845f;
#pragma unroll
    for (int i = 0; i < 16; i++) {
        int idx = t + i * 256;          // 4096 = 128 rows x 32 d2-pairs
        int r = idx >> 5;
        int d2 = (idx & 31) * 2;
        float x1a = sf[r * 132 + d2],      x1b = sf[r * 132 + d2 + 1];
        float x2a = sf[r * 132 + d2 + 64], x2b = sf[r * 132 + d2 + 65];
        float y1a, y1b, y2a, y2b;
        if (hq < NQH + NKVH) {
            float pos = (float)positions[m0 + r];
            float fa = pos * powf(10000.0f, -((float)(2 * d2)) / 128.0f);
            float fb = pos * powf(10000.0f, -((float)(2 * (d2 + 1))) / 128.0f);
            float ca = cosf(fa), sa = sinf(fa);
            float cb = cosf(fb), sb = sinf(fb);
            y1a = x1a * ca - x2a * sa; y2a = x2a * ca + x1a * sa;
            y1b = x1b * cb - x2b * sb; y2b = x2b * cb + x1b * sb;
            if (hq < NQH) { y1a *= qscale; y1b *= qscale; y2a *= qscale; y2b *= qscale; }
        } else {
            y1a = x1a; y1b = x1b; y2a = x2a; y2b = x2b;
        }
        uint32_t h1, mm1, h2, mm2;
        split2(y1a, y1b, h1, mm1);
        split2(y2a, y2b, h2, mm2);
        if (hq < NQH) {
            size_t o = (size_t)(m0 + r) * Q_SIZE + hq * HD + d2;
            *(uint32_t*)(g_q_hi + o)       = h1;  *(uint32_t*)(g_q_mid + o)       = mm1;
            *(uint32_t*)(g_q_hi + o + 64)  = h2;  *(uint32_t*)(g_q_mid + o + 64)  = mm2;
        } else if (hq < NQH + NKVH) {
            size_t o = ((size_t)(hq - NQH) * S_LEN + (m0 + r)) * HD + d2;
            *(uint32_t*)(g_k_hi + o)       = h1;  *(uint32_t*)(g_k_mid + o)       = mm1;
            *(uint32_t*)(g_k_hi + o + 64)  = h2;  *(uint32_t*)(g_k_mid + o + 64)  = mm2;
        } else {
            size_t o = ((size_t)(hq - NQH - NKVH) * S_LEN + (m0 + r)) * HD + d2;
            *(uint32_t*)(g_v_hi + o)       = h1;  *(uint32_t*)(g_v_mid + o)       = mm1;
            *(uint32_t*)(g_v_hi + o + 64)  = h2;  *(uint32_t*)(g_v_mid + o + 64)  = mm2;
        }
    }
}

// ---------------------------------------------------------------------------
// Tensorized flash attention, pre-split bf16 operands, 2-stage cp.async KV.
// ---------------------------------------------------------------------------
#define FSTR 272
#define FQ_B  (128 * FSTR)            // 34816
#define FK_B  (64 * FSTR)             // 17408
#define KVSTAGE_B (4 * FK_B)          // 69632
#define FLASH_SMEM (2 * FQ_B + 2 * KVSTAGE_B)   // 208896

__device__ __forceinline__ void flash_issue_kv(uint32_t dstbase, int kvh, int n0, int t) {
    const __nv_bfloat16* s0 = g_k_hi  + ((size_t)kvh * S_LEN + n0) * HD;
    const __nv_bfloat16* s1 = g_k_mid + ((size_t)kvh * S_LEN + n0) * HD;
    const __nv_bfloat16* s2 = g_v_hi  + ((size_t)kvh * S_LEN + n0) * HD;
    const __nv_bfloat16* s3 = g_v_mid + ((size_t)kvh * S_LEN + n0) * HD;
    const __nv_bfloat16* srcs[4] = {s0, s1, s2, s3};
#pragma unroll
    for (int i = 0; i < 16; i++) {
        int idx = t + i * 256;          // 4096 chunks of 16B
        int arr = idx >> 10;
        int within = idx & 1023;
        int r = within >> 4, c = within & 15;
        cp_async16(dstbase + arr * FK_B + (uint32_t)r * FSTR + c * 16,
                   srcs[arr] + (size_t)r * HD + c * 8);
    }
}

__global__ __launch_bounds__(256) void flash_mma_kernel() {
    extern __shared__ char fsm[];
    uint32_t uQ  = smem_u32(fsm);
    uint32_t uKV = uQ + 2 * FQ_B;

    int qt = 15 - (int)blockIdx.x;        // heavy tiles first
    int h  = blockIdx.y;
    int kvh = h >> 2;
    int t = threadIdx.x;
    int lane = t & 31, wid = t >> 5;
    int q0 = qt * 128;

    // issue Q (hi+mid) + KV stage 0, one commit group
    {
        const __nv_bfloat16* qh = g_q_hi  + (size_t)q0 * Q_SIZE + h * HD;
        const __nv_bfloat16* qm = g_q_mid + (size_t)q0 * Q_SIZE + h * HD;
#pragma unroll
        for (int i = 0; i < 16; i++) {
            int idx = t + i * 256;         // 4096 chunks: [hi 2048][mid 2048]
            int arr = idx >> 11;
            int within = idx & 2047;
            int r = within >> 4, c = within & 15;
            const __nv_bfloat16* src = (arr == 0 ? qh : qm) + (size_t)r * Q_SIZE + c * 8;
            cp_async16(uQ + arr * FQ_B + (uint32_t)r * FSTR + c * 16, src);
        }
        flash_issue_kv(uKV, kvh, 0, t);
        cp_commit();
    }

    float rm0 = -1e30f, rm1 = -1e30f, rl0 = 0.f, rl1 = 0.f;
    float o[16][4];
#pragma unroll
    for (int i = 0; i < 16; i++)
#pragma unroll
        for (int j = 0; j < 4; j++) o[i][j] = 0.f;

    int ktmax = 2 * qt + 1;
    for (int kt = 0; kt <= ktmax; kt++) {
        int n0 = kt * 64;
        if (kt + 1 <= ktmax) {
            flash_issue_kv(uKV + ((kt + 1) & 1) * KVSTAGE_B, kvh, (kt + 1) * 64, t);
            cp_commit();
            cp_wait1();
        } else {
            cp_wait0();
        }
        __syncthreads();

        uint32_t uK = uKV + (kt & 1) * KVSTAGE_B;   // K hi
        uint32_t uV = uK + 2 * FK_B;                // V hi

        // S = Q K^T  (warp: m16 x n64)
        float s[8][4];
#pragma unroll
        for (int i = 0; i < 8; i++)
#pragma unroll
            for (int j = 0; j < 4; j++) s[i][j] = 0.f;

        int q = lane >> 3;
        uint32_t brow = ((q & 2) << 2) + (lane & 7);
        uint32_t bko  = (uint32_t)((q & 1) << 4);
#pragma unroll
        for (int kc = 0; kc < 8; kc++) {
            uint32_t ah[4], am[4];
            uint32_t aaddr = uQ + (uint32_t)(wid * 16 + (lane & 15)) * FSTR + kc * 32 + ((lane >> 4) << 4);
            LDSM4(ah, aaddr);
            LDSM4(am, aaddr + FQ_B);
#pragma unroll
            for (int g = 0; g < 4; g++) {
                uint32_t bh[4], bm[4];
                uint32_t baddr = uK + (uint32_t)(g * 16 + brow) * FSTR + kc * 32 + bko;
                LDSM4(bh, baddr);
                LDSM4(bm, baddr + FK_B);
                MMA16816(s[2*g],   ah, bh[0], bh[1]);
                MMA16816(s[2*g],   ah, bm[0], bm[1]);
                MMA16816(s[2*g],   am, bh[0], bh[1]);
                MMA16816(s[2*g+1], ah, bh[2], bh[3]);
                MMA16816(s[2*g+1], ah, bm[2], bm[3]);
                MMA16816(s[2*g+1], am, bh[2], bh[3]);
            }
        }

        int r0g = q0 + wid * 16 + (lane >> 2);
        if (kt >= 2 * qt) {
#pragma unroll
            for (int nf = 0; nf < 8; nf++) {
                int c0 = n0 + nf * 8 + (lane & 3) * 2;
                if (c0     > r0g)     s[nf][0] = -1e30f;
                if (c0 + 1 > r0g)     s[nf][1] = -1e30f;
                if (c0     > r0g + 8) s[nf][2] = -1e30f;
                if (c0 + 1 > r0g + 8) s[nf][3] = -1e30f;
            }
        }
        float mx0 = -1e30f, mx1 = -1e30f;
#pragma unroll
        for (int nf = 0; nf < 8; nf++) {
            mx0 = fmaxf(mx0, fmaxf(s[nf][0], s[nf][1]));
            mx1 = fmaxf(mx1, fmaxf(s[nf][2], s[nf][3]));
        }
        mx0 = fmaxf(mx0, __shfl_xor_sync(0xffffffffu, mx0, 1));
        mx0 = fmaxf(mx0, __shfl_xor_sync(0xffffffffu, mx0, 2));
        mx1 = fmaxf(mx1, __shfl_xor_sync(0xffffffffu, mx1, 1));
        mx1 = fmaxf(mx1, __shfl_xor_sync(0xffffffffu, mx1, 2));
        float mn0 = fmaxf(rm0, mx0), mn1 = fmaxf(rm1, mx1);
        float cr0 = __expf(rm0 - mn0), cr1 = __expf(rm1 - mn1);
        rm0 = mn0; rm1 = mn1;

        uint32_t pah[4][4], pam[4][4];
        float ls0 = 0.f, ls1 = 0.f;
#pragma unroll
        for (int g = 0; g < 4; g++) {
            float pA0 = __expf(s[2*g][0]   - mn0), pA1 = __expf(s[2*g][1]   - mn0);
            float pA2 = __expf(s[2*g][2]   - mn1), pA3 = __expf(s[2*g][3]   - mn1);
            float pB0 = __expf(s[2*g+1][0] - mn0), pB1 = __expf(s[2*g+1][1] - mn0);
            float pB2 = __expf(s[2*g+1][2] - mn1), pB3 = __expf(s[2*g+1][3] - mn1);
            ls0 += pA0 + pA1 + pB0 + pB1;
            ls1 += pA2 + pA3 + pB2 + pB3;
            split2(pA0, pA1, pah[g][0], pam[g][0]);
            split2(pA2, pA3, pah[g][1], pam[g][1]);
            split2(pB0, pB1, pah[g][2], pam[g][2]);
            split2(pB2, pB3, pah[g][3], pam[g][3]);
        }
        ls0 += __shfl_xor_sync(0xffffffffu, ls0, 1);
        ls0 += __shfl_xor_sync(0xffffffffu, ls0, 2);
        ls1 += __shfl_xor_sync(0xffffffffu, ls1, 1);
        ls1 += __shfl_xor_sync(0xffffffffu, ls1, 2);
        rl0 = rl0 * cr0 + ls0;
        rl1 = rl1 * cr1 + ls1;

#pragma unroll
        for (int nf = 0; nf < 16; nf++) {
            o[nf][0] *= cr0; o[nf][1] *= cr0;
            o[nf][2] *= cr1; o[nf][3] *= cr1;
        }

        // O += P V   (B frags via ldmatrix.trans on V[kv][d])
#pragma unroll
        for (int g = 0; g < 4; g++) {
#pragma unroll
            for (int dg = 0; dg < 8; dg++) {
                uint32_t bh[4], bm[4];
                uint32_t vaddr = uV + (uint32_t)(g * 16 + (lane & 15)) * FSTR + dg * 32 + ((lane >> 4) << 4);
                LDSM4T(bh, vaddr);
                LDSM4T(bm, vaddr + FK_B);
                MMA16816(o[2*dg],   pah[g], bh[0], bh[1]);
                MMA16816(o[2*dg],   pah[g], bm[0], bm[1]);
                MMA16816(o[2*dg],   pam[g], bh[0], bh[1]);
                MMA16816(o[2*dg+1], pah[g], bh[2], bh[3]);
                MMA16816(o[2*dg+1], pah[g], bm[2], bm[3]);
                MMA16816(o[2*dg+1], pam[g], bh[2], bh[3]);
            }
        }
        __syncthreads();   // reads of this stage done before its buffer is re-issued
    }

    // epilogue: normalize, split hi/mid, store
    float li0 = 1.f / rl0, li1 = 1.f / rl1;
    int r = q0 + wid * 16 + (lane >> 2);
    __nv_bfloat16* goh = g_attn_hi  + (size_t)r * Q_SIZE + h * HD + (lane & 3) * 2;
    __nv_bfloat16* gom = g_attn_mid + (size_t)r * Q_SIZE + h * HD + (lane & 3) * 2;
#pragma unroll
    for (int nf = 0; nf < 16; nf++) {
        uint32_t h0, m0, h1, m1;
        split2(o[nf][0] * li0, o[nf][1] * li0, h0, m0);
        split2(o[nf][2] * li1, o[nf][3] * li1, h1, m1);
        *(uint32_t*)(goh + nf * 8)                      = h0;
        *(uint32_t*)(gom + nf * 8)                      = m0;
        *(uint32_t*)(goh + (size_t)8 * Q_SIZE + nf * 8) = h1;
        *(uint32_t*)(gom + (size_t)8 * Q_SIZE + nf * 8) = m1;
    }
}

// ---------------------------------------------------------------------------
extern "C" void kernel_launch(void* const* d_in, const int* in_sizes, int n_in,
                              void* d_out, int out_size) {
    const int*   positions = (const int*)d_in[0];
    const float* hidden    = (const float*)d_in[1];
    const float* lnw       = (const float*)d_in[2];
    const float* w_qkv     = (const float*)d_in[3];
    const float* w_o       = (const float*)d_in[4];
    float* out = (float*)d_out;

    void* p;
    cudaGetSymbolAddress(&p, g_xn_hi);    __nv_bfloat16* xnh = (__nv_bfloat16*)p;
    cudaGetSymbolAddress(&p, g_xn_mid);   __nv_bfloat16* xnm = (__nv_bfloat16*)p;
    cudaGetSymbolAddress(&p, g_wqkv_hi);  __nv_bfloat16* wqh = (__nv_bfloat16*)p;
    cudaGetSymbolAddress(&p, g_wqkv_mid); __nv_bfloat16* wqm = (__nv_bfloat16*)p;
    cudaGetSymbolAddress(&p, g_wo_hi);    __nv_bfloat16* woh = (__nv_bfloat16*)p;
    cudaGetSymbolAddress(&p, g_wo_mid);   __nv_bfloat16* wom = (__nv_bfloat16*)p;
    cudaGetSymbolAddress(&p, g_attn_hi);  __nv_bfloat16* ath = (__nv_bfloat16*)p;
    cudaGetSymbolAddress(&p, g_attn_mid); __nv_bfloat16* atm = (__nv_bfloat16*)p;

    cudaFuncSetAttribute(gemm_mma_kernel, cudaFuncAttributeMaxDynamicSharedMemorySize, GEMM_SMEM);
    cudaFuncSetAttribute(flash_mma_kernel, cudaFuncAttributeMaxDynamicSharedMemorySize, FLASH_SMEM);

    // split weights to bf16 hi/mid
    split_kernel<<<(QKV_N * HID / 4 + 255) / 256, 256>>>(w_qkv, wqh, wqm, QKV_N * HID / 4);
    split_kernel<<<(Q_SIZE * HID / 4 + 255) / 256, 256>>>(w_o, woh, wom, Q_SIZE * HID / 4);

    // 1. RMSNorm -> xn hi/mid
    rmsnorm_kernel<<<S_LEN, 256>>>(hidden, lnw);

    // 2. QKV GEMM with fused RoPE+scale+split epilogue -> g_q/g_k/g_v hi/mid
    {
        dim3 grid(QKV_N / 128, S_LEN / 128);
        gemm_mma_kernel<<<grid, 256, GEMM_SMEM>>>(xnh, xnm, wqh, wqm,
                                                  nullptr, HID, QKV_N, 1, positions);
    }

    // 3. Tensorized flash attention (pipelined bf16 loads) -> attn hi/mid
    {
        dim3 grid(S_LEN / 128, NQH);
        flash_mma_kernel<<<grid, 256, FLASH_SMEM>>>();
    }

    // 4. out = attn @ w_o^T (HMMA split) -> d_out fp32
    {
        dim3 grid(Q_SIZE / 128, S_LEN / 128);
        gemm_mma_kernel<<<grid, 256, GEMM_SMEM>>>(ath, atm, woh, wom,
                                                  out, HID, Q_SIZE, 0, positions);
    }
    (void)in_sizes; (void)n_in; (void)out_size;
}